// round 1
// baseline (speedup 1.0000x reference)
#include <cuda_runtime.h>

// Deterministic two-stage reduction for 0.5 * sum((d1-d2)^2).
// Stage 1: 1184 blocks (one full wave on 148 SMs at 8x256 thr) each produce one
//          partial in a __device__ global (no cudaMalloc allowed).
// Stage 2: single block tree-sums the 1184 partials, scales by 0.5, writes out[0].
// No atomics -> bitwise-deterministic across replays (harness requirement).

#define GRID_BLOCKS 1184
#define BLOCK_THREADS 256

__device__ float g_partials[GRID_BLOCKS];

__global__ void __launch_bounds__(BLOCK_THREADS)
mse_partial_kernel(const float4* __restrict__ a,
                   const float4* __restrict__ b,
                   int n4, const float* __restrict__ a_s,
                   const float* __restrict__ b_s, int n)
{
    float acc = 0.0f;
    const int stride = gridDim.x * blockDim.x;
    int i = blockIdx.x * blockDim.x + threadIdx.x;

    #pragma unroll 4
    for (; i < n4; i += stride) {
        float4 x = a[i];
        float4 y = b[i];
        float d0 = x.x - y.x;
        float d1 = x.y - y.y;
        float d2 = x.z - y.z;
        float d3 = x.w - y.w;
        acc = fmaf(d0, d0, acc);
        acc = fmaf(d1, d1, acc);
        acc = fmaf(d2, d2, acc);
        acc = fmaf(d3, d3, acc);
    }

    // Scalar tail (n not multiple of 4) — handled by global thread 0 only.
    if (blockIdx.x == 0 && threadIdx.x == 0) {
        for (int t = n4 * 4; t < n; ++t) {
            float d = a_s[t] - b_s[t];
            acc = fmaf(d, d, acc);
        }
    }

    // Warp reduce
    #pragma unroll
    for (int o = 16; o > 0; o >>= 1)
        acc += __shfl_down_sync(0xffffffffu, acc, o);

    __shared__ float smem[BLOCK_THREADS / 32];
    const int lane = threadIdx.x & 31;
    const int wid  = threadIdx.x >> 5;
    if (lane == 0) smem[wid] = acc;
    __syncthreads();

    if (wid == 0) {
        acc = (lane < BLOCK_THREADS / 32) ? smem[lane] : 0.0f;
        #pragma unroll
        for (int o = 16; o > 0; o >>= 1)
            acc += __shfl_down_sync(0xffffffffu, acc, o);
        if (lane == 0) g_partials[blockIdx.x] = acc;
    }
}

__global__ void __launch_bounds__(BLOCK_THREADS)
mse_final_kernel(float* __restrict__ out)
{
    float acc = 0.0f;
    for (int i = threadIdx.x; i < GRID_BLOCKS; i += BLOCK_THREADS)
        acc += g_partials[i];

    #pragma unroll
    for (int o = 16; o > 0; o >>= 1)
        acc += __shfl_down_sync(0xffffffffu, acc, o);

    __shared__ float smem[BLOCK_THREADS / 32];
    const int lane = threadIdx.x & 31;
    const int wid  = threadIdx.x >> 5;
    if (lane == 0) smem[wid] = acc;
    __syncthreads();

    if (wid == 0) {
        acc = (lane < BLOCK_THREADS / 32) ? smem[lane] : 0.0f;
        #pragma unroll
        for (int o = 16; o > 0; o >>= 1)
            acc += __shfl_down_sync(0xffffffffu, acc, o);
        if (lane == 0) out[0] = 0.5f * acc;
    }
}

extern "C" void kernel_launch(void* const* d_in, const int* in_sizes, int n_in,
                              void* d_out, int out_size)
{
    const float* d1 = (const float*)d_in[0];
    const float* d2 = (const float*)d_in[1];
    float* out = (float*)d_out;

    const int n  = in_sizes[0];   // 40,000,000
    const int n4 = n >> 2;

    mse_partial_kernel<<<GRID_BLOCKS, BLOCK_THREADS>>>(
        (const float4*)d1, (const float4*)d2, n4, d1, d2, n);
    mse_final_kernel<<<1, BLOCK_THREADS>>>(out);
}